// round 13
// baseline (speedup 1.0000x reference)
#include <cuda_runtime.h>

#define BATCH 4096
#define PC 2380
#define PCROW1 (PC + PC + 1)   // 4761: PC-code row for plane 1
#define RW 16            // padded row width (15 cols + ghost)
#define STR2 244         // channel stride in floats (mult of 4)

// ---- smem layout (float offsets) ----
#define OFF_CB    0      // 48   conv_b
#define OFF_VSUM  48     // 32
#define OFF_CODES 80     // 450 ints -> 530 (pad to 532)
#define OFF_WPPT  532    // 256   ppw transposed [ci][co]
#define OFF_WVPT  788    // 1024  vpw transposed [ci][co]
#define OFF_PCR   1812   // 96    emb rows for PC codes (plane0 @0, plane1 @48)
#define OFF_STAG  1908   // 768   gather staging: 16 slots x 48 ch (pos-major)
#define OFF_RAW   2676   // 48*244 = 11712 ; depthwise IN PLACE; pol-pw IN PLACE rows 0..15
#define SMEM_FLOATS 14388
#define SMEM_BYTES  (SMEM_FLOATS * 4)

typedef unsigned long long ull;

__device__ __forceinline__ void ffma2(ull& d, ull a, ull b) {
    asm("fma.rn.f32x2 %0, %1, %2, %0;" : "+l"(d) : "l"(a), "l"(b));
}
__device__ __forceinline__ ull pk2(float x, float y) {
    ull r; asm("mov.b64 %0, {%1, %2};" : "=l"(r) : "f"(x), "f"(y)); return r;
}
__device__ __forceinline__ float2 unpk(ull v) {
    float2 f; asm("mov.b64 {%0, %1}, %2;" : "=f"(f.x), "=f"(f.y) : "l"(v)); return f;
}

// depthwise 3x3, one channel, 4-col strip, rows [H0,H1), sliding register window.
// Safe in-place (src==dst): row h+1 loaded before row h stored; all 4 strips of a
// channel sit in one warp (lockstep). wk may point to GLOBAL memory.
template<int H0, int H1>
__device__ __forceinline__ void dwconv4(const float* src, float* dst,
                                        const float* __restrict__ wk,
                                        float bias, int wg)
{
    const int w0 = wg * 4;
    const bool hasL = (wg > 0), hasR = (wg < 3);
    const float k0=wk[0],k1=wk[1],k2=wk[2],k3=wk[3],k4=wk[4],k5=wk[5],k6=wk[6],k7=wk[7],k8=wk[8];
    float al,a0,a1,a2,a3,ar, bl,b0,b1,b2,b3,br;
    if (H0 > 0) {
        const float* r = src + (H0 - 1) * RW;
        float4 m = *(const float4*)(r + w0);
        al = hasL ? r[w0 - 1] : 0.f;  ar = hasR ? r[w0 + 4] : 0.f;
        a0 = m.x; a1 = m.y; a2 = m.z; a3 = m.w;
    } else { al=a0=a1=a2=a3=ar=0.f; }
    {
        const float* r = src + H0 * RW;
        float4 m = *(const float4*)(r + w0);
        bl = hasL ? r[w0 - 1] : 0.f;  br = hasR ? r[w0 + 4] : 0.f;
        b0 = m.x; b1 = m.y; b2 = m.z; b3 = m.w;
    }
    #pragma unroll
    for (int h = H0; h < H1; h++) {
        float cl, c0, c1, c2, c3, cr;
        if (h + 1 < 15) {
            const float* r = src + (h + 1) * RW;
            float4 m = *(const float4*)(r + w0);
            cl = hasL ? r[w0 - 1] : 0.f;  cr = hasR ? r[w0 + 4] : 0.f;
            c0 = m.x; c1 = m.y; c2 = m.z; c3 = m.w;
        } else { cl = c0 = c1 = c2 = c3 = cr = 0.f; }
        float o0 = bias + al*k0+a0*k1+a1*k2 + bl*k3+b0*k4+b1*k5 + cl*k6+c0*k7+c1*k8;
        float o1 = bias + a0*k0+a1*k1+a2*k2 + b0*k3+b1*k4+b2*k5 + c0*k6+c1*k7+c2*k8;
        float o2 = bias + a1*k0+a2*k1+a3*k2 + b1*k3+b2*k4+b3*k5 + c1*k6+c2*k7+c3*k8;
        float o3 = bias + a2*k0+a3*k1+ar*k2 + b2*k3+b3*k4+br*k5 + c2*k6+c3*k7+cr*k8;
        *(float4*)(dst + h * RW + w0) =
            make_float4(fmaxf(o0,0.f), fmaxf(o1,0.f), fmaxf(o2,0.f), fmaxf(o3,0.f));
        al=bl; a0=b0; a1=b1; a2=b2; a3=b3; ar=br;
        bl=cl; b0=c0; b1=c1; b2=c2; b3=c3; br=cr;
    }
}

extern "C" __global__ void __launch_bounds__(256, 4)
patnet_kernel(const float* __restrict__ emb,
              const float* __restrict__ conv_w, const float* __restrict__ conv_b,
              const float* __restrict__ ppw_w,  const float* __restrict__ ppw_b,
              const float* __restrict__ pdw_w,  const float* __restrict__ pdw_b,
              const float* __restrict__ pf_w,
              const float* __restrict__ vpw_w,  const float* __restrict__ vpw_b,
              const float* __restrict__ vl1_w,  const float* __restrict__ vl1_b,
              const float* __restrict__ vl2_w,  const float* __restrict__ vl2_b,
              const float* __restrict__ vf_w,   const float* __restrict__ vf_b,
              const int* __restrict__ sparse,   const int* __restrict__ board,
              float* __restrict__ out)
{
    extern __shared__ float sm[];
    float* cb   = sm + OFF_CB;
    float* vsum = sm + OFF_VSUM;
    int*   codes= (int*)(sm + OFF_CODES);
    float* wppT = sm + OFF_WPPT;
    float* wvpT = sm + OFF_WVPT;
    float* pcr  = sm + OFF_PCR;
    float* stag = sm + OFF_STAG;
    float* raw  = sm + OFF_RAW;
    float* conv = raw;                 // main depthwise IN PLACE
    float* pp   = raw;                 // policy pointwise IN PLACE on rows 0..15
    float* pd   = raw + 16 * STR2;     // value rows 16..31, dead after P3a

    const int tid = threadIdx.x;
    const int b   = blockIdx.x;
    const int lane = tid & 31;

    // ---------- P0: small weights -> smem, PC rows, codes ----------
    for (int i = tid; i < 48;  i += 256) cb[i]  = conv_b[i];
    if (tid >= 64 && tid < 96) vsum[tid-64] = 0.0f;
    if (tid >= 96 && tid < 144) pcr[tid - 96]      = emb[PC * 48 + (tid - 96)];
    if (tid >= 144 && tid < 192) pcr[48 + tid-144] = emb[PCROW1 * 48 + (tid - 144)];
    for (int i = tid; i < 256; i += 256) {
        int co = i >> 4, ci = i & 15;
        wppT[ci * 16 + co] = ppw_w[i];
    }
    for (int i = tid; i < 1024; i += 256) {
        int co = i >> 5, ci = i & 31;
        wvpT[ci * 32 + co] = vpw_w[i];
    }
    for (int i = tid; i < 450; i += 256) {
        int j = i / 225, p = i - j * 225;
        int sp = sparse[b * 2700 + (10 + j) * 225 + p];
        int bd = board[b * 450 + j * 225 + p];
        int c = (bd > 0) ? PC : sp;
        codes[i] = c + j * (PC + 1);
    }
    __syncthreads();

    // ---------- P1: staged gather, one board row per round ----------
    // PC-coded lanes read the cached smem row (no gmem sectors); others LDG.
    #pragma unroll 1
    for (int r = 0; r < 15; r++) {
        if (tid < 192) {
            const int sl = tid / 12, q = tid - sl * 12;   // sl = w (0..15), q = quarter
            float4 v = make_float4(0.f, 0.f, 0.f, 0.f);
            if (sl < 15) {
                const int p = r * 15 + sl;
                const int c0 = codes[p], c1 = codes[225 + p];
                float4 a, b2;
                if (c0 == PC) a = *(const float4*)&pcr[q * 4];
                else          a = *(const float4*)(emb + c0 * 48 + q * 4);
                if (c1 == PCROW1) b2 = *(const float4*)&pcr[48 + q * 4];
                else              b2 = *(const float4*)(emb + c1 * 48 + q * 4);
                v = make_float4(a.x + b2.x, a.y + b2.y, a.z + b2.z, a.w + b2.w);
            }
            *(float4*)&stag[sl * 48 + q * 4] = v;
        }
        __syncthreads();
        if (tid < 192) {
            const int g = tid / 48, c = tid - g * 48;     // g = slot-group, c = channel
            float4 o;
            o.x = stag[(4*g + 0) * 48 + c];
            o.y = stag[(4*g + 1) * 48 + c];
            o.z = stag[(4*g + 2) * 48 + c];
            o.w = stag[(4*g + 3) * 48 + c];
            *(float4*)&raw[c * STR2 + r * RW + 4 * g] = o;
        }
        __syncthreads();
    }

    // ---------- P2: main depthwise 3x3, 48 ch, 192 threads, IN PLACE ----------
    if (tid < 192) {
        const int c = tid >> 2, wg = tid & 3;
        dwconv4<0, 15>(raw + c * STR2, conv + c * STR2, conv_w + c * 9, cb[c], wg);
    }
    __syncthreads();

    // ---------- P3a: value 1x1 32->32, f32x2, S=8 C=4, all 256 threads ----------
    {
        const int cg = tid & 7, pgi = tid >> 3;
        const bool live = (pgi < 30);
        const int p0 = live ? pgi * 8 : 0;
        const int co0 = cg * 4;
        ull acc[4][4];
        {
            float4 bv = *(const float4*)&vpw_b[co0];
            ull b0 = pk2(bv.x, bv.x), b1 = pk2(bv.y, bv.y);
            ull b2 = pk2(bv.z, bv.z), b3 = pk2(bv.w, bv.w);
            #pragma unroll
            for (int j = 0; j < 4; j++) {
                acc[j][0] = b0; acc[j][1] = b1; acc[j][2] = b2; acc[j][3] = b3;
            }
        }
        #pragma unroll 8
        for (int ci = 0; ci < 32; ci++) {
            const ulonglong2* ip = (const ulonglong2*)&conv[(16 + ci) * STR2 + p0];
            float4 w4 = *(const float4*)&wvpT[ci * 32 + co0];
            ull w0 = pk2(w4.x, w4.x), w1 = pk2(w4.y, w4.y);
            ull w2 = pk2(w4.z, w4.z), w3 = pk2(w4.w, w4.w);
            {
                ulonglong2 iA = ip[0];
                ffma2(acc[0][0], iA.x, w0); ffma2(acc[1][0], iA.y, w0);
                ffma2(acc[0][1], iA.x, w1); ffma2(acc[1][1], iA.y, w1);
                ffma2(acc[0][2], iA.x, w2); ffma2(acc[1][2], iA.y, w2);
                ffma2(acc[0][3], iA.x, w3); ffma2(acc[1][3], iA.y, w3);
            }
            {
                ulonglong2 iB = ip[1];
                ffma2(acc[2][0], iB.x, w0); ffma2(acc[3][0], iB.y, w0);
                ffma2(acc[2][1], iB.x, w1); ffma2(acc[3][1], iB.y, w1);
                ffma2(acc[2][2], iB.x, w2); ffma2(acc[3][2], iB.y, w2);
                ffma2(acc[2][3], iB.x, w3); ffma2(acc[3][3], iB.y, w3);
            }
        }
        #pragma unroll
        for (int k = 0; k < 4; k++) {
            float s = 0.0f;
            #pragma unroll
            for (int j = 0; j < 4; j++) {
                float2 f = unpk(acc[j][k]);
                int s0 = p0 + 2 * j;
                if (live && ((s0 & 15) != 15))       s += fmaxf(f.x, 0.0f);
                if (live && (((s0 + 1) & 15) != 15)) s += fmaxf(f.y, 0.0f);
            }
            s += __shfl_xor_sync(0xffffffffu, s, 8);
            s += __shfl_xor_sync(0xffffffffu, s, 16);
            if (lane < 8) atomicAdd(&vsum[lane * 4 + k], s);
        }
    }

    // ---------- P3b: policy 1x1 16->16, IN PLACE on rows 0..15, tid<120 ----------
    if (tid < 120) {
        const int pgi = tid >> 2, cg = tid & 3;
        const int p0 = pgi * 8, co0 = cg * 4;
        ull acc[4][4];
        {
            float4 bv = *(const float4*)&ppw_b[co0];
            ull b0 = pk2(bv.x, bv.x), b1 = pk2(bv.y, bv.y);
            ull b2 = pk2(bv.z, bv.z), b3 = pk2(bv.w, bv.w);
            #pragma unroll
            for (int j = 0; j < 4; j++) {
                acc[j][0] = b0; acc[j][1] = b1; acc[j][2] = b2; acc[j][3] = b3;
            }
        }
        #pragma unroll
        for (int ci = 0; ci < 16; ci++) {
            const ulonglong2* ip = (const ulonglong2*)&conv[ci * STR2 + p0];
            ulonglong2 iA = ip[0], iB = ip[1];
            float4 w4 = *(const float4*)&wppT[ci * 16 + co0];
            ull w0 = pk2(w4.x, w4.x), w1 = pk2(w4.y, w4.y);
            ull w2 = pk2(w4.z, w4.z), w3 = pk2(w4.w, w4.w);
            ffma2(acc[0][0], iA.x, w0); ffma2(acc[1][0], iA.y, w0);
            ffma2(acc[2][0], iB.x, w0); ffma2(acc[3][0], iB.y, w0);
            ffma2(acc[0][1], iA.x, w1); ffma2(acc[1][1], iA.y, w1);
            ffma2(acc[2][1], iB.x, w1); ffma2(acc[3][1], iB.y, w1);
            ffma2(acc[0][2], iA.x, w2); ffma2(acc[1][2], iA.y, w2);
            ffma2(acc[2][2], iB.x, w2); ffma2(acc[3][2], iB.y, w2);
            ffma2(acc[0][3], iA.x, w3); ffma2(acc[1][3], iA.y, w3);
            ffma2(acc[2][3], iB.x, w3); ffma2(acc[3][3], iB.y, w3);
        }
        const bool ghost = ((p0 & 15) == 8);   // slot p0+7 is ghost
        #pragma unroll
        for (int k = 0; k < 4; k++) {
            float2 f0 = unpk(acc[0][k]), f1 = unpk(acc[1][k]);
            float2 f2 = unpk(acc[2][k]), f3 = unpk(acc[3][k]);
            float4 oA = make_float4(fmaxf(f0.x,0.f), fmaxf(f0.y,0.f),
                                    fmaxf(f1.x,0.f), fmaxf(f1.y,0.f));
            float4 oB = make_float4(fmaxf(f2.x,0.f), fmaxf(f2.y,0.f),
                                    fmaxf(f3.x,0.f), ghost ? 0.f : fmaxf(f3.y,0.f));
            float* dstc = pp + (co0 + k) * STR2 + p0;
            *(float4*)(dstc)     = oA;
            *(float4*)(dstc + 4) = oB;
        }
    }
    __syncthreads();

    // ---------- P4: policy depthwise (tid<128, row-split) | value FC (warp 7) ----------
    if (tid < 128) {
        const int c = tid >> 3, sub = tid & 7;
        const int wg = sub & 3, half = sub >> 2;
        const float bias = pdw_b[c];
        if (half == 0)
            dwconv4<0, 8>(pp + c * STR2, pd + c * STR2, pdw_w + c * 9, bias, wg);
        else
            dwconv4<8, 15>(pp + c * STR2, pd + c * STR2, pdw_w + c * 9, bias, wg);
    }
    if (tid >= 224) {
        const int l = lane;
        float v = vsum[l] * (1.0f / 225.0f);
        float h1 = vl1_b[l];
        #pragma unroll
        for (int i = 0; i < 32; i++)
            h1 += vl1_w[l * 32 + i] * __shfl_sync(0xffffffffu, v, i);
        h1 = fmaxf(h1, 0.0f);
        float h2 = vl2_b[l];
        #pragma unroll
        for (int i = 0; i < 32; i++)
            h2 += vl2_w[l * 32 + i] * __shfl_sync(0xffffffffu, h1, i);
        h2 = fmaxf(h2, 0.0f);
        float o = (l < 3) ? vf_b[l] : 0.0f;
        #pragma unroll
        for (int i = 0; i < 32; i++) {
            float t = __shfl_sync(0xffffffffu, h2, i);
            if (l < 3) o += vf_w[l * 32 + i] * t;
        }
        if (l < 3) out[b * 3 + l] = o;
    }
    __syncthreads();

    // ---------- P5: pf 16->1, f32x2, tid<120 (2 slots each) ----------
    if (tid < 120) {
        const int s0 = 2 * tid;
        const float4 wfA = *(const float4*)(pf_w);
        const float4 wfB = *(const float4*)(pf_w + 4);
        const float4 wfC = *(const float4*)(pf_w + 8);
        const float4 wfD = *(const float4*)(pf_w + 12);
        const float wf[16] = {wfA.x,wfA.y,wfA.z,wfA.w, wfB.x,wfB.y,wfB.z,wfB.w,
                              wfC.x,wfC.y,wfC.z,wfC.w, wfD.x,wfD.y,wfD.z,wfD.w};
        ull acc = 0;
        #pragma unroll
        for (int ci = 0; ci < 16; ci++) {
            ull iv = *(const ull*)&pd[ci * STR2 + s0];
            ffma2(acc, iv, pk2(wf[ci], wf[ci]));
        }
        float2 f = unpk(acc);
        const int w = s0 & 15, h = s0 >> 4;
        float* ob = out + BATCH * 3 + b * 225 + h * 15 + w;
        ob[0] = f.x;
        if (w < 14) ob[1] = f.y;
    }
}

extern "C" void kernel_launch(void* const* d_in, const int* in_sizes, int n_in,
                              void* d_out, int out_size) {
    (void)in_sizes; (void)n_in; (void)out_size;
    cudaFuncSetAttribute(patnet_kernel,
                         cudaFuncAttributeMaxDynamicSharedMemorySize, SMEM_BYTES);
    patnet_kernel<<<BATCH, 256, SMEM_BYTES>>>(
        (const float*)d_in[0],  (const float*)d_in[1],  (const float*)d_in[2],
        (const float*)d_in[3],  (const float*)d_in[4],  (const float*)d_in[5],
        (const float*)d_in[6],  (const float*)d_in[7],  (const float*)d_in[8],
        (const float*)d_in[9],  (const float*)d_in[10], (const float*)d_in[11],
        (const float*)d_in[12], (const float*)d_in[13], (const float*)d_in[14],
        (const float*)d_in[15], (const int*)d_in[16],   (const int*)d_in[17],
        (float*)d_out);
}

// round 14
// speedup vs baseline: 1.0988x; 1.0988x over previous
#include <cuda_runtime.h>

#define BATCH 4096
#define PC 2380
#define PCROW1 (PC + PC + 1)   // 4761: PC-code row for plane 1
#define RW 16            // padded row width (15 cols + ghost)
#define STR2 244         // channel stride in floats (mult of 4)

// ---- smem layout (float offsets) ----  total identical to R12 (4 CTA/SM)
#define OFF_VSUM  0      // 32
#define OFF_CODES 32     // 450 ints -> 482 (pad 484)
#define OFF_WPPT  484    // 256   ppw transposed [ci][co]
#define OFF_WVPT  740    // 1024  vpw transposed [ci][co]
#define OFF_PCR   1764   // 96    emb rows for PC codes (plane0 @0, plane1 @48)
#define OFF_STAG  1860   // 720   gather staging: 15 slots x 48 ch (pos-major)
#define OFF_RAW   2580   // 48*244 = 11712 ; depthwise IN PLACE; pol-pw IN PLACE rows 0..15
#define SMEM_FLOATS 14292
#define SMEM_BYTES  (SMEM_FLOATS * 4)

typedef unsigned long long ull;

__device__ __forceinline__ void ffma2(ull& d, ull a, ull b) {
    asm("fma.rn.f32x2 %0, %1, %2, %0;" : "+l"(d) : "l"(a), "l"(b));
}
__device__ __forceinline__ ull pk2(float x, float y) {
    ull r; asm("mov.b64 %0, {%1, %2};" : "=l"(r) : "f"(x), "f"(y)); return r;
}
__device__ __forceinline__ float2 unpk(ull v) {
    float2 f; asm("mov.b64 {%0, %1}, %2;" : "=f"(f.x), "=f"(f.y) : "l"(v)); return f;
}

// depthwise 3x3, one channel, 4-col strip, rows [H0,H1), sliding register window.
// Safe in-place (src==dst): row h+1 loaded before row h stored; all 4 strips of a
// channel sit in one warp (lockstep). wk may point to GLOBAL memory.
template<int H0, int H1>
__device__ __forceinline__ void dwconv4(const float* src, float* dst,
                                        const float* __restrict__ wk,
                                        float bias, int wg)
{
    const int w0 = wg * 4;
    const bool hasL = (wg > 0), hasR = (wg < 3);
    const float k0=wk[0],k1=wk[1],k2=wk[2],k3=wk[3],k4=wk[4],k5=wk[5],k6=wk[6],k7=wk[7],k8=wk[8];
    float al,a0,a1,a2,a3,ar, bl,b0,b1,b2,b3,br;
    if (H0 > 0) {
        const float* r = src + (H0 - 1) * RW;
        float4 m = *(const float4*)(r + w0);
        al = hasL ? r[w0 - 1] : 0.f;  ar = hasR ? r[w0 + 4] : 0.f;
        a0 = m.x; a1 = m.y; a2 = m.z; a3 = m.w;
    } else { al=a0=a1=a2=a3=ar=0.f; }
    {
        const float* r = src + H0 * RW;
        float4 m = *(const float4*)(r + w0);
        bl = hasL ? r[w0 - 1] : 0.f;  br = hasR ? r[w0 + 4] : 0.f;
        b0 = m.x; b1 = m.y; b2 = m.z; b3 = m.w;
    }
    #pragma unroll
    for (int h = H0; h < H1; h++) {
        float cl, c0, c1, c2, c3, cr;
        if (h + 1 < 15) {
            const float* r = src + (h + 1) * RW;
            float4 m = *(const float4*)(r + w0);
            cl = hasL ? r[w0 - 1] : 0.f;  cr = hasR ? r[w0 + 4] : 0.f;
            c0 = m.x; c1 = m.y; c2 = m.z; c3 = m.w;
        } else { cl = c0 = c1 = c2 = c3 = cr = 0.f; }
        float o0 = bias + al*k0+a0*k1+a1*k2 + bl*k3+b0*k4+b1*k5 + cl*k6+c0*k7+c1*k8;
        float o1 = bias + a0*k0+a1*k1+a2*k2 + b0*k3+b1*k4+b2*k5 + c0*k6+c1*k7+c2*k8;
        float o2 = bias + a1*k0+a2*k1+a3*k2 + b1*k3+b2*k4+b3*k5 + c1*k6+c2*k7+c3*k8;
        float o3 = bias + a2*k0+a3*k1+ar*k2 + b2*k3+b3*k4+br*k5 + c2*k6+c3*k7+cr*k8;
        *(float4*)(dst + h * RW + w0) =
            make_float4(fmaxf(o0,0.f), fmaxf(o1,0.f), fmaxf(o2,0.f), fmaxf(o3,0.f));
        al=bl; a0=b0; a1=b1; a2=b2; a3=b3; ar=br;
        bl=cl; b0=c0; b1=c1; b2=c2; b3=c3; br=cr;
    }
}

extern "C" __global__ void __launch_bounds__(256, 4)
patnet_kernel(const float* __restrict__ emb,
              const float* __restrict__ conv_w, const float* __restrict__ conv_b,
              const float* __restrict__ ppw_w,  const float* __restrict__ ppw_b,
              const float* __restrict__ pdw_w,  const float* __restrict__ pdw_b,
              const float* __restrict__ pf_w,
              const float* __restrict__ vpw_w,  const float* __restrict__ vpw_b,
              const float* __restrict__ vl1_w,  const float* __restrict__ vl1_b,
              const float* __restrict__ vl2_w,  const float* __restrict__ vl2_b,
              const float* __restrict__ vf_w,   const float* __restrict__ vf_b,
              const int* __restrict__ sparse,   const int* __restrict__ board,
              float* __restrict__ out)
{
    extern __shared__ float sm[];
    float* vsum = sm + OFF_VSUM;
    int*   codes= (int*)(sm + OFF_CODES);
    float* wppT = sm + OFF_WPPT;
    float* wvpT = sm + OFF_WVPT;
    float* pcr  = sm + OFF_PCR;
    float* stag = sm + OFF_STAG;
    float* raw  = sm + OFF_RAW;
    float* conv = raw;                 // main depthwise IN PLACE
    float* pp   = raw;                 // policy pointwise IN PLACE on rows 0..15
    float* pd   = raw + 16 * STR2;     // value rows 16..31, dead after P3a

    const int tid = threadIdx.x;
    const int b   = blockIdx.x;
    const int lane = tid & 31;

    // ---------- P0: small weights -> smem, PC rows, codes ----------
    if (tid >= 64 && tid < 96) vsum[tid-64] = 0.0f;
    if (tid >= 96 && tid < 144) pcr[tid - 96]       = emb[PC * 48 + (tid - 96)];
    if (tid >= 144 && tid < 192) pcr[48 + tid-144]  = emb[PCROW1 * 48 + (tid - 144)];
    for (int i = tid; i < 256; i += 256) {
        int co = i >> 4, ci = i & 15;
        wppT[ci * 16 + co] = ppw_w[i];
    }
    for (int i = tid; i < 1024; i += 256) {
        int co = i >> 5, ci = i & 31;
        wvpT[ci * 32 + co] = vpw_w[i];
    }
    for (int i = tid; i < 450; i += 256) {
        int j = i / 225, p = i - j * 225;
        int sp = sparse[b * 2700 + (10 + j) * 225 + p];
        int bd = board[b * 450 + j * 225 + p];
        int c = (bd > 0) ? PC : sp;
        codes[i] = c + j * (PC + 1);
    }
    __syncthreads();

    // ---------- P1: staged gather, one board row per round ----------
    // PC-coded lanes read the cached smem row (no gmem sectors); others LDG.
    #pragma unroll 1
    for (int r = 0; r < 15; r++) {
        if (tid < 180) {
            const int sl = tid / 12, q = tid - sl * 12;   // sl = w (0..14), q = quarter
            const int p = r * 15 + sl;
            const int c0 = codes[p], c1 = codes[225 + p];
            float4 a, b2;
            if (c0 == PC) a = *(const float4*)&pcr[q * 4];
            else          a = *(const float4*)(emb + c0 * 48 + q * 4);
            if (c1 == PCROW1) b2 = *(const float4*)&pcr[48 + q * 4];
            else              b2 = *(const float4*)(emb + c1 * 48 + q * 4);
            *(float4*)&stag[sl * 48 + q * 4] =
                make_float4(a.x + b2.x, a.y + b2.y, a.z + b2.z, a.w + b2.w);
        }
        __syncthreads();
        if (tid < 192) {
            const int g = tid / 48, c = tid - g * 48;     // g = slot-group, c = channel
            float4 o;
            o.x = stag[(4*g + 0) * 48 + c];
            o.y = stag[(4*g + 1) * 48 + c];
            o.z = stag[(4*g + 2) * 48 + c];
            o.w = (g < 3) ? stag[(4*g + 3) * 48 + c] : 0.0f;   // slot 15 = ghost
            *(float4*)&raw[c * STR2 + r * RW + 4 * g] = o;
        }
        __syncthreads();
    }

    // ---------- P2: main depthwise 3x3, 48 ch, 192 threads, IN PLACE ----------
    if (tid < 192) {
        const int c = tid >> 2, wg = tid & 3;
        dwconv4<0, 15>(raw + c * STR2, conv + c * STR2, conv_w + c * 9, conv_b[c], wg);
    }
    __syncthreads();

    // ---------- P3a: value 1x1 32->32, f32x2, S=8 C=4, all 256 threads ----------
    {
        const int cg = tid & 7, pgi = tid >> 3;
        const bool live = (pgi < 30);
        const int p0 = live ? pgi * 8 : 0;
        const int co0 = cg * 4;
        ull acc[4][4];
        {
            float4 bv = *(const float4*)&vpw_b[co0];
            ull b0 = pk2(bv.x, bv.x), b1 = pk2(bv.y, bv.y);
            ull b2 = pk2(bv.z, bv.z), b3 = pk2(bv.w, bv.w);
            #pragma unroll
            for (int j = 0; j < 4; j++) {
                acc[j][0] = b0; acc[j][1] = b1; acc[j][2] = b2; acc[j][3] = b3;
            }
        }
        #pragma unroll 8
        for (int ci = 0; ci < 32; ci++) {
            const ulonglong2* ip = (const ulonglong2*)&conv[(16 + ci) * STR2 + p0];
            float4 w4 = *(const float4*)&wvpT[ci * 32 + co0];
            ull w0 = pk2(w4.x, w4.x), w1 = pk2(w4.y, w4.y);
            ull w2 = pk2(w4.z, w4.z), w3 = pk2(w4.w, w4.w);
            {
                ulonglong2 iA = ip[0];
                ffma2(acc[0][0], iA.x, w0); ffma2(acc[1][0], iA.y, w0);
                ffma2(acc[0][1], iA.x, w1); ffma2(acc[1][1], iA.y, w1);
                ffma2(acc[0][2], iA.x, w2); ffma2(acc[1][2], iA.y, w2);
                ffma2(acc[0][3], iA.x, w3); ffma2(acc[1][3], iA.y, w3);
            }
            {
                ulonglong2 iB = ip[1];
                ffma2(acc[2][0], iB.x, w0); ffma2(acc[3][0], iB.y, w0);
                ffma2(acc[2][1], iB.x, w1); ffma2(acc[3][1], iB.y, w1);
                ffma2(acc[2][2], iB.x, w2); ffma2(acc[3][2], iB.y, w2);
                ffma2(acc[2][3], iB.x, w3); ffma2(acc[3][3], iB.y, w3);
            }
        }
        #pragma unroll
        for (int k = 0; k < 4; k++) {
            float s = 0.0f;
            #pragma unroll
            for (int j = 0; j < 4; j++) {
                float2 f = unpk(acc[j][k]);
                int s0 = p0 + 2 * j;
                if (live && ((s0 & 15) != 15))       s += fmaxf(f.x, 0.0f);
                if (live && (((s0 + 1) & 15) != 15)) s += fmaxf(f.y, 0.0f);
            }
            s += __shfl_xor_sync(0xffffffffu, s, 8);
            s += __shfl_xor_sync(0xffffffffu, s, 16);
            if (lane < 8) atomicAdd(&vsum[lane * 4 + k], s);
        }
    }

    // ---------- P3b: policy 1x1 16->16, IN PLACE on rows 0..15, tid<120 ----------
    if (tid < 120) {
        const int pgi = tid >> 2, cg = tid & 3;
        const int p0 = pgi * 8, co0 = cg * 4;
        ull acc[4][4];
        {
            float4 bv = *(const float4*)&ppw_b[co0];
            ull b0 = pk2(bv.x, bv.x), b1 = pk2(bv.y, bv.y);
            ull b2 = pk2(bv.z, bv.z), b3 = pk2(bv.w, bv.w);
            #pragma unroll
            for (int j = 0; j < 4; j++) {
                acc[j][0] = b0; acc[j][1] = b1; acc[j][2] = b2; acc[j][3] = b3;
            }
        }
        #pragma unroll
        for (int ci = 0; ci < 16; ci++) {
            const ulonglong2* ip = (const ulonglong2*)&conv[ci * STR2 + p0];
            ulonglong2 iA = ip[0], iB = ip[1];
            float4 w4 = *(const float4*)&wppT[ci * 16 + co0];
            ull w0 = pk2(w4.x, w4.x), w1 = pk2(w4.y, w4.y);
            ull w2 = pk2(w4.z, w4.z), w3 = pk2(w4.w, w4.w);
            ffma2(acc[0][0], iA.x, w0); ffma2(acc[1][0], iA.y, w0);
            ffma2(acc[2][0], iB.x, w0); ffma2(acc[3][0], iB.y, w0);
            ffma2(acc[0][1], iA.x, w1); ffma2(acc[1][1], iA.y, w1);
            ffma2(acc[2][1], iB.x, w1); ffma2(acc[3][1], iB.y, w1);
            ffma2(acc[0][2], iA.x, w2); ffma2(acc[1][2], iA.y, w2);
            ffma2(acc[2][2], iB.x, w2); ffma2(acc[3][2], iB.y, w2);
            ffma2(acc[0][3], iA.x, w3); ffma2(acc[1][3], iA.y, w3);
            ffma2(acc[2][3], iB.x, w3); ffma2(acc[3][3], iB.y, w3);
        }
        const bool ghost = ((p0 & 15) == 8);   // slot p0+7 is ghost
        #pragma unroll
        for (int k = 0; k < 4; k++) {
            float2 f0 = unpk(acc[0][k]), f1 = unpk(acc[1][k]);
            float2 f2 = unpk(acc[2][k]), f3 = unpk(acc[3][k]);
            float4 oA = make_float4(fmaxf(f0.x,0.f), fmaxf(f0.y,0.f),
                                    fmaxf(f1.x,0.f), fmaxf(f1.y,0.f));
            float4 oB = make_float4(fmaxf(f2.x,0.f), fmaxf(f2.y,0.f),
                                    fmaxf(f3.x,0.f), ghost ? 0.f : fmaxf(f3.y,0.f));
            float* dstc = pp + (co0 + k) * STR2 + p0;
            *(float4*)(dstc)     = oA;
            *(float4*)(dstc + 4) = oB;
        }
    }
    __syncthreads();

    // ---------- P4: policy depthwise (tid<128, row-split) | value FC (warp 7) ----------
    if (tid < 128) {
        const int c = tid >> 3, sub = tid & 7;
        const int wg = sub & 3, half = sub >> 2;
        const float bias = pdw_b[c];
        if (half == 0)
            dwconv4<0, 8>(pp + c * STR2, pd + c * STR2, pdw_w + c * 9, bias, wg);
        else
            dwconv4<8, 15>(pp + c * STR2, pd + c * STR2, pdw_w + c * 9, bias, wg);
    }
    if (tid >= 224) {
        const int l = lane;
        float v = vsum[l] * (1.0f / 225.0f);
        float h1 = vl1_b[l];
        #pragma unroll
        for (int i = 0; i < 32; i++)
            h1 += vl1_w[l * 32 + i] * __shfl_sync(0xffffffffu, v, i);
        h1 = fmaxf(h1, 0.0f);
        float h2 = vl2_b[l];
        #pragma unroll
        for (int i = 0; i < 32; i++)
            h2 += vl2_w[l * 32 + i] * __shfl_sync(0xffffffffu, h1, i);
        h2 = fmaxf(h2, 0.0f);
        float o = (l < 3) ? vf_b[l] : 0.0f;
        #pragma unroll
        for (int i = 0; i < 32; i++) {
            float t = __shfl_sync(0xffffffffu, h2, i);
            if (l < 3) o += vf_w[l * 32 + i] * t;
        }
        if (l < 3) out[b * 3 + l] = o;
    }
    __syncthreads();

    // ---------- P5: pf 16->1, f32x2, tid<120 (2 slots each) ----------
    if (tid < 120) {
        const int s0 = 2 * tid;
        const float4 wfA = *(const float4*)(pf_w);
        const float4 wfB = *(const float4*)(pf_w + 4);
        const float4 wfC = *(const float4*)(pf_w + 8);
        const float4 wfD = *(const float4*)(pf_w + 12);
        const float wf[16] = {wfA.x,wfA.y,wfA.z,wfA.w, wfB.x,wfB.y,wfB.z,wfB.w,
                              wfC.x,wfC.y,wfC.z,wfC.w, wfD.x,wfD.y,wfD.z,wfD.w};
        ull acc = 0;
        #pragma unroll
        for (int ci = 0; ci < 16; ci++) {
            ull iv = *(const ull*)&pd[ci * STR2 + s0];
            ffma2(acc, iv, pk2(wf[ci], wf[ci]));
        }
        float2 f = unpk(acc);
        const int w = s0 & 15, h = s0 >> 4;
        float* ob = out + BATCH * 3 + b * 225 + h * 15 + w;
        ob[0] = f.x;
        if (w < 14) ob[1] = f.y;
    }
}

extern "C" void kernel_launch(void* const* d_in, const int* in_sizes, int n_in,
                              void* d_out, int out_size) {
    (void)in_sizes; (void)n_in; (void)out_size;
    cudaFuncSetAttribute(patnet_kernel,
                         cudaFuncAttributeMaxDynamicSharedMemorySize, SMEM_BYTES);
    patnet_kernel<<<BATCH, 256, SMEM_BYTES>>>(
        (const float*)d_in[0],  (const float*)d_in[1],  (const float*)d_in[2],
        (const float*)d_in[3],  (const float*)d_in[4],  (const float*)d_in[5],
        (const float*)d_in[6],  (const float*)d_in[7],  (const float*)d_in[8],
        (const float*)d_in[9],  (const float*)d_in[10], (const float*)d_in[11],
        (const float*)d_in[12], (const float*)d_in[13], (const float*)d_in[14],
        (const float*)d_in[15], (const int*)d_in[16],   (const int*)d_in[17],
        (float*)d_out);
}

// round 15
// speedup vs baseline: 1.1526x; 1.0490x over previous
#include <cuda_runtime.h>

#define BATCH 4096
#define PC 2380
#define PCROW1 (PC + PC + 1)   // 4761: PC-code row for plane 1
#define RW 16            // padded row width (15 cols + ghost)
#define STR2 244         // channel stride in floats (mult of 4)

// ---- smem layout (float offsets) ----  4 CTA/SM
#define OFF_VSUM  0      // 32
#define OFF_CODES 32     // 450 ints -> 482 (pad 484)
#define OFF_WPPT  484    // 256   ppw transposed [ci][co]
#define OFF_WVPT  740    // 1024  vpw transposed [ci][co]
#define OFF_PCR   1764   // 96    emb rows for PC codes (plane0 @0, plane1 @48)
#define OFF_STAG  1860   // 720   gather staging: 15 slots x 48 ch (pos-major)
#define OFF_RAW   2580   // 48*244 = 11712 ; depthwise IN PLACE; pol-pw IN PLACE rows 0..15
#define SMEM_FLOATS 14292
#define SMEM_BYTES  (SMEM_FLOATS * 4)

typedef unsigned long long ull;

__device__ __forceinline__ void ffma2(ull& d, ull a, ull b) {
    asm("fma.rn.f32x2 %0, %1, %2, %0;" : "+l"(d) : "l"(a), "l"(b));
}
__device__ __forceinline__ ull pk2(float x, float y) {
    ull r; asm("mov.b64 %0, {%1, %2};" : "=l"(r) : "f"(x), "f"(y)); return r;
}
__device__ __forceinline__ float2 unpk(ull v) {
    float2 f; asm("mov.b64 {%0, %1}, %2;" : "=f"(f.x), "=f"(f.y) : "l"(v)); return f;
}

// depthwise 3x3, one channel, 4-col strip, rows [H0,H1), sliding register window.
// Edge columns come from neighbor lanes via shuffle (lane-1 holds strip wg-1,
// lane+1 holds strip wg+1 of the SAME channel; cross-channel/boundary shuffles
// are nulled by hasL/hasR). mask = participating lanes (all share H0/H1).
// Safe in-place (src==dst): row h+1 loaded before row h stored; all strips of a
// channel-half sit in the mask (lockstep). wk may point to GLOBAL memory.
template<int H0, int H1>
__device__ __forceinline__ void dwconv4s(const float* src, float* dst,
                                         const float* __restrict__ wk,
                                         float bias, int wg, unsigned mask)
{
    const int w0 = wg * 4;
    const bool hasL = (wg > 0), hasR = (wg < 3);
    const float k0=wk[0],k1=wk[1],k2=wk[2],k3=wk[3],k4=wk[4],k5=wk[5],k6=wk[6],k7=wk[7],k8=wk[8];
    float al,a0,a1,a2,a3,ar, bl,b0,b1,b2,b3,br;
    if (H0 > 0) {
        float4 m = *(const float4*)(src + (H0 - 1) * RW + w0);
        float lw = __shfl_up_sync(mask, m.w, 1);
        float rw = __shfl_down_sync(mask, m.x, 1);
        al = hasL ? lw : 0.f;  ar = hasR ? rw : 0.f;
        a0 = m.x; a1 = m.y; a2 = m.z; a3 = m.w;
    } else { al=a0=a1=a2=a3=ar=0.f; }
    {
        float4 m = *(const float4*)(src + H0 * RW + w0);
        float lw = __shfl_up_sync(mask, m.w, 1);
        float rw = __shfl_down_sync(mask, m.x, 1);
        bl = hasL ? lw : 0.f;  br = hasR ? rw : 0.f;
        b0 = m.x; b1 = m.y; b2 = m.z; b3 = m.w;
    }
    #pragma unroll
    for (int h = H0; h < H1; h++) {
        float cl, c0, c1, c2, c3, cr;
        if (h + 1 < 15) {
            float4 m = *(const float4*)(src + (h + 1) * RW + w0);
            float lw = __shfl_up_sync(mask, m.w, 1);
            float rw = __shfl_down_sync(mask, m.x, 1);
            cl = hasL ? lw : 0.f;  cr = hasR ? rw : 0.f;
            c0 = m.x; c1 = m.y; c2 = m.z; c3 = m.w;
        } else { cl = c0 = c1 = c2 = c3 = cr = 0.f; }
        float o0 = bias + al*k0+a0*k1+a1*k2 + bl*k3+b0*k4+b1*k5 + cl*k6+c0*k7+c1*k8;
        float o1 = bias + a0*k0+a1*k1+a2*k2 + b0*k3+b1*k4+b2*k5 + c0*k6+c1*k7+c2*k8;
        float o2 = bias + a1*k0+a2*k1+a3*k2 + b1*k3+b2*k4+b3*k5 + c1*k6+c2*k7+c3*k8;
        float o3 = bias + a2*k0+a3*k1+ar*k2 + b2*k3+b3*k4+br*k5 + c2*k6+c3*k7+cr*k8;
        *(float4*)(dst + h * RW + w0) =
            make_float4(fmaxf(o0,0.f), fmaxf(o1,0.f), fmaxf(o2,0.f), fmaxf(o3,0.f));
        al=bl; a0=b0; a1=b1; a2=b2; a3=b3; ar=br;
        bl=cl; b0=c0; b1=c1; b2=c2; b3=c3; br=cr;
    }
}

extern "C" __global__ void __launch_bounds__(256, 4)
patnet_kernel(const float* __restrict__ emb,
              const float* __restrict__ conv_w, const float* __restrict__ conv_b,
              const float* __restrict__ ppw_w,  const float* __restrict__ ppw_b,
              const float* __restrict__ pdw_w,  const float* __restrict__ pdw_b,
              const float* __restrict__ pf_w,
              const float* __restrict__ vpw_w,  const float* __restrict__ vpw_b,
              const float* __restrict__ vl1_w,  const float* __restrict__ vl1_b,
              const float* __restrict__ vl2_w,  const float* __restrict__ vl2_b,
              const float* __restrict__ vf_w,   const float* __restrict__ vf_b,
              const int* __restrict__ sparse,   const int* __restrict__ board,
              float* __restrict__ out)
{
    extern __shared__ float sm[];
    float* vsum = sm + OFF_VSUM;
    int*   codes= (int*)(sm + OFF_CODES);
    float* wppT = sm + OFF_WPPT;
    float* wvpT = sm + OFF_WVPT;
    float* pcr  = sm + OFF_PCR;
    float* stag = sm + OFF_STAG;
    float* raw  = sm + OFF_RAW;
    float* conv = raw;                 // main depthwise IN PLACE
    float* pp   = raw;                 // policy pointwise IN PLACE on rows 0..15
    float* pd   = raw + 16 * STR2;     // value rows 16..31, dead after P3a

    const int tid = threadIdx.x;
    const int b   = blockIdx.x;
    const int lane = tid & 31;

    // ---------- P0: small weights -> smem, PC rows, codes ----------
    if (tid >= 64 && tid < 96) vsum[tid-64] = 0.0f;
    if (tid >= 96 && tid < 144) pcr[tid - 96]       = emb[PC * 48 + (tid - 96)];
    if (tid >= 144 && tid < 192) pcr[48 + tid-144]  = emb[PCROW1 * 48 + (tid - 144)];
    for (int i = tid; i < 256; i += 256) {
        int co = i >> 4, ci = i & 15;
        wppT[ci * 16 + co] = ppw_w[i];
    }
    for (int i = tid; i < 1024; i += 256) {
        int co = i >> 5, ci = i & 31;
        wvpT[ci * 32 + co] = vpw_w[i];
    }
    for (int i = tid; i < 450; i += 256) {
        int j = i / 225, p = i - j * 225;
        int sp = sparse[b * 2700 + (10 + j) * 225 + p];
        int bd = board[b * 450 + j * 225 + p];
        int c = (bd > 0) ? PC : sp;
        codes[i] = c + j * (PC + 1);
    }
    __syncthreads();

    // ---------- P1: staged gather, one board row per round ----------
    #pragma unroll 1
    for (int r = 0; r < 15; r++) {
        if (tid < 180) {
            const int sl = tid / 12, q = tid - sl * 12;   // sl = w (0..14), q = quarter
            const int p = r * 15 + sl;
            const int c0 = codes[p], c1 = codes[225 + p];
            float4 a, b2;
            if (c0 == PC) a = *(const float4*)&pcr[q * 4];
            else          a = *(const float4*)(emb + c0 * 48 + q * 4);
            if (c1 == PCROW1) b2 = *(const float4*)&pcr[48 + q * 4];
            else              b2 = *(const float4*)(emb + c1 * 48 + q * 4);
            *(float4*)&stag[sl * 48 + q * 4] =
                make_float4(a.x + b2.x, a.y + b2.y, a.z + b2.z, a.w + b2.w);
        }
        __syncthreads();
        if (tid < 192) {
            const int g = tid / 48, c = tid - g * 48;     // g = slot-group, c = channel
            float4 o;
            o.x = stag[(4*g + 0) * 48 + c];
            o.y = stag[(4*g + 1) * 48 + c];
            o.z = stag[(4*g + 2) * 48 + c];
            o.w = (g < 3) ? stag[(4*g + 3) * 48 + c] : 0.0f;   // slot 15 = ghost
            *(float4*)&raw[c * STR2 + r * RW + 4 * g] = o;
        }
        __syncthreads();
    }

    // ---------- P2: main depthwise 3x3, 48 ch, 192 threads, IN PLACE, shfl edges ----
    if (tid < 192) {
        const int c = tid >> 2, wg = tid & 3;
        dwconv4s<0, 15>(raw + c * STR2, conv + c * STR2, conv_w + c * 9, conv_b[c],
                        wg, 0xffffffffu);
    }
    __syncthreads();

    // ---------- P3a: value 1x1 32->32, f32x2, S=8 C=4, all 256 threads ----------
    {
        const int cg = tid & 7, pgi = tid >> 3;
        const bool live = (pgi < 30);
        const int p0 = live ? pgi * 8 : 0;
        const int co0 = cg * 4;
        ull acc[4][4];
        {
            float4 bv = *(const float4*)&vpw_b[co0];
            ull b0 = pk2(bv.x, bv.x), b1 = pk2(bv.y, bv.y);
            ull b2 = pk2(bv.z, bv.z), b3 = pk2(bv.w, bv.w);
            #pragma unroll
            for (int j = 0; j < 4; j++) {
                acc[j][0] = b0; acc[j][1] = b1; acc[j][2] = b2; acc[j][3] = b3;
            }
        }
        #pragma unroll 8
        for (int ci = 0; ci < 32; ci++) {
            const ulonglong2* ip = (const ulonglong2*)&conv[(16 + ci) * STR2 + p0];
            float4 w4 = *(const float4*)&wvpT[ci * 32 + co0];
            ull w0 = pk2(w4.x, w4.x), w1 = pk2(w4.y, w4.y);
            ull w2 = pk2(w4.z, w4.z), w3 = pk2(w4.w, w4.w);
            {
                ulonglong2 iA = ip[0];
                ffma2(acc[0][0], iA.x, w0); ffma2(acc[1][0], iA.y, w0);
                ffma2(acc[0][1], iA.x, w1); ffma2(acc[1][1], iA.y, w1);
                ffma2(acc[0][2], iA.x, w2); ffma2(acc[1][2], iA.y, w2);
                ffma2(acc[0][3], iA.x, w3); ffma2(acc[1][3], iA.y, w3);
            }
            {
                ulonglong2 iB = ip[1];
                ffma2(acc[2][0], iB.x, w0); ffma2(acc[3][0], iB.y, w0);
                ffma2(acc[2][1], iB.x, w1); ffma2(acc[3][1], iB.y, w1);
                ffma2(acc[2][2], iB.x, w2); ffma2(acc[3][2], iB.y, w2);
                ffma2(acc[2][3], iB.x, w3); ffma2(acc[3][3], iB.y, w3);
            }
        }
        #pragma unroll
        for (int k = 0; k < 4; k++) {
            float s = 0.0f;
            #pragma unroll
            for (int j = 0; j < 4; j++) {
                float2 f = unpk(acc[j][k]);
                int s0 = p0 + 2 * j;
                if (live && ((s0 & 15) != 15))       s += fmaxf(f.x, 0.0f);
                if (live && (((s0 + 1) & 15) != 15)) s += fmaxf(f.y, 0.0f);
            }
            s += __shfl_xor_sync(0xffffffffu, s, 8);
            s += __shfl_xor_sync(0xffffffffu, s, 16);
            if (lane < 8) atomicAdd(&vsum[lane * 4 + k], s);
        }
    }

    // ---------- P3b: policy 1x1 16->16, IN PLACE on rows 0..15, tid<120 ----------
    if (tid < 120) {
        const int pgi = tid >> 2, cg = tid & 3;
        const int p0 = pgi * 8, co0 = cg * 4;
        ull acc[4][4];
        {
            float4 bv = *(const float4*)&ppw_b[co0];
            ull b0 = pk2(bv.x, bv.x), b1 = pk2(bv.y, bv.y);
            ull b2 = pk2(bv.z, bv.z), b3 = pk2(bv.w, bv.w);
            #pragma unroll
            for (int j = 0; j < 4; j++) {
                acc[j][0] = b0; acc[j][1] = b1; acc[j][2] = b2; acc[j][3] = b3;
            }
        }
        #pragma unroll
        for (int ci = 0; ci < 16; ci++) {
            const ulonglong2* ip = (const ulonglong2*)&conv[ci * STR2 + p0];
            ulonglong2 iA = ip[0], iB = ip[1];
            float4 w4 = *(const float4*)&wppT[ci * 16 + co0];
            ull w0 = pk2(w4.x, w4.x), w1 = pk2(w4.y, w4.y);
            ull w2 = pk2(w4.z, w4.z), w3 = pk2(w4.w, w4.w);
            ffma2(acc[0][0], iA.x, w0); ffma2(acc[1][0], iA.y, w0);
            ffma2(acc[2][0], iB.x, w0); ffma2(acc[3][0], iB.y, w0);
            ffma2(acc[0][1], iA.x, w1); ffma2(acc[1][1], iA.y, w1);
            ffma2(acc[2][1], iB.x, w1); ffma2(acc[3][1], iB.y, w1);
            ffma2(acc[0][2], iA.x, w2); ffma2(acc[1][2], iA.y, w2);
            ffma2(acc[2][2], iB.x, w2); ffma2(acc[3][2], iB.y, w2);
            ffma2(acc[0][3], iA.x, w3); ffma2(acc[1][3], iA.y, w3);
            ffma2(acc[2][3], iB.x, w3); ffma2(acc[3][3], iB.y, w3);
        }
        const bool ghost = ((p0 & 15) == 8);   // slot p0+7 is ghost
        #pragma unroll
        for (int k = 0; k < 4; k++) {
            float2 f0 = unpk(acc[0][k]), f1 = unpk(acc[1][k]);
            float2 f2 = unpk(acc[2][k]), f3 = unpk(acc[3][k]);
            float4 oA = make_float4(fmaxf(f0.x,0.f), fmaxf(f0.y,0.f),
                                    fmaxf(f1.x,0.f), fmaxf(f1.y,0.f));
            float4 oB = make_float4(fmaxf(f2.x,0.f), fmaxf(f2.y,0.f),
                                    fmaxf(f3.x,0.f), ghost ? 0.f : fmaxf(f3.y,0.f));
            float* dstc = pp + (co0 + k) * STR2 + p0;
            *(float4*)(dstc)     = oA;
            *(float4*)(dstc + 4) = oB;
        }
    }
    __syncthreads();

    // ---------- P4: policy depthwise (tid<128, row-split, masked shfl) | value FC ----
    if (tid < 128) {
        const int c = tid >> 3, sub = tid & 7;
        const int wg = sub & 3, half = sub >> 2;
        const float bias = pdw_b[c];
        if (half == 0)
            dwconv4s<0, 8>(pp + c * STR2, pd + c * STR2, pdw_w + c * 9, bias,
                           wg, 0x0F0F0F0Fu);
        else
            dwconv4s<8, 15>(pp + c * STR2, pd + c * STR2, pdw_w + c * 9, bias,
                            wg, 0xF0F0F0F0u);
    }
    if (tid >= 224) {
        const int l = lane;
        float v = vsum[l] * (1.0f / 225.0f);
        float h1 = vl1_b[l];
        #pragma unroll
        for (int i = 0; i < 32; i++)
            h1 += vl1_w[l * 32 + i] * __shfl_sync(0xffffffffu, v, i);
        h1 = fmaxf(h1, 0.0f);
        float h2 = vl2_b[l];
        #pragma unroll
        for (int i = 0; i < 32; i++)
            h2 += vl2_w[l * 32 + i] * __shfl_sync(0xffffffffu, h1, i);
        h2 = fmaxf(h2, 0.0f);
        float o = (l < 3) ? vf_b[l] : 0.0f;
        #pragma unroll
        for (int i = 0; i < 32; i++) {
            float t = __shfl_sync(0xffffffffu, h2, i);
            if (l < 3) o += vf_w[l * 32 + i] * t;
        }
        if (l < 3) out[b * 3 + l] = o;
    }
    __syncthreads();

    // ---------- P5: pf 16->1, f32x2, tid<120 (2 slots each) ----------
    if (tid < 120) {
        const int s0 = 2 * tid;
        const float4 wfA = *(const float4*)(pf_w);
        const float4 wfB = *(const float4*)(pf_w + 4);
        const float4 wfC = *(const float4*)(pf_w + 8);
        const float4 wfD = *(const float4*)(pf_w + 12);
        const float wf[16] = {wfA.x,wfA.y,wfA.z,wfA.w, wfB.x,wfB.y,wfB.z,wfB.w,
                              wfC.x,wfC.y,wfC.z,wfC.w, wfD.x,wfD.y,wfD.z,wfD.w};
        ull acc = 0;
        #pragma unroll
        for (int ci = 0; ci < 16; ci++) {
            ull iv = *(const ull*)&pd[ci * STR2 + s0];
            ffma2(acc, iv, pk2(wf[ci], wf[ci]));
        }
        float2 f = unpk(acc);
        const int w = s0 & 15, h = s0 >> 4;
        float* ob = out + BATCH * 3 + b * 225 + h * 15 + w;
        ob[0] = f.x;
        if (w < 14) ob[1] = f.y;
    }
}

extern "C" void kernel_launch(void* const* d_in, const int* in_sizes, int n_in,
                              void* d_out, int out_size) {
    (void)in_sizes; (void)n_in; (void)out_size;
    cudaFuncSetAttribute(patnet_kernel,
                         cudaFuncAttributeMaxDynamicSharedMemorySize, SMEM_BYTES);
    patnet_kernel<<<BATCH, 256, SMEM_BYTES>>>(
        (const float*)d_in[0],  (const float*)d_in[1],  (const float*)d_in[2],
        (const float*)d_in[3],  (const float*)d_in[4],  (const float*)d_in[5],
        (const float*)d_in[6],  (const float*)d_in[7],  (const float*)d_in[8],
        (const float*)d_in[9],  (const float*)d_in[10], (const float*)d_in[11],
        (const float*)d_in[12], (const float*)d_in[13], (const float*)d_in[14],
        (const float*)d_in[15], (const int*)d_in[16],   (const int*)d_in[17],
        (float*)d_out);
}